// round 13
// baseline (speedup 1.0000x reference)
#include <cuda_runtime.h>
#include <cuda_bf16.h>
#include <cstdint>

#define N_NODES 50000
#define N_EDGES 600000
#define DIM     128
#define LN_EPS  1e-5f
#define N_TILES ((N_NODES + 127) / 128)   // 391
#define SCAN_BLOCKS 49                    // 49 * 1024 >= 50000

// ---------------------------------------------------------------------------
// Scratch (device globals: allocation-free per harness rules)
// ---------------------------------------------------------------------------
__device__ float g_agg[N_NODES * DIM];
__device__ float g_degout[N_NODES];
__device__ float g_degin[N_NODES];
__device__ float g_outnorm[N_NODES];
__device__ float g_innorm[N_NODES];
__device__ int   g_part[N_NODES];
__device__ int   g_bsum[64];
__device__ int   g_off[N_NODES + 1];
__device__ int   g_cursor[N_NODES];
__device__ int   g_ssrc[N_EDGES];
// B tiles (bf16, plain [n][k] layout): [h0_hi | h0_lo | h1_hi | h1_lo]
__device__ __align__(16) uint8_t g_Bt[4 * 32768];

// ---------------------------------------------------------------------------
// bf16 hi/lo split helpers
// ---------------------------------------------------------------------------
__device__ __forceinline__ void split_bf16(float x, uint16_t& hi, uint16_t& lo) {
    __nv_bfloat16 h = __float2bfloat16(x);
    hi = __bfloat16_as_ushort(h);
    float hf = __uint_as_float((uint32_t)hi << 16);
    lo = __bfloat16_as_ushort(__float2bfloat16(x - hf));
}
__device__ __forceinline__ void split2(float x0, float x1, uint32_t& hi2, uint32_t& lo2) {
    __nv_bfloat162 h = __floats2bfloat162_rn(x0, x1);
    hi2 = *reinterpret_cast<uint32_t*>(&h);
    float hf0 = __uint_as_float(hi2 << 16);
    float hf1 = __uint_as_float(hi2 & 0xFFFF0000u);
    __nv_bfloat162 l = __floats2bfloat162_rn(x0 - hf0, x1 - hf1);
    lo2 = *reinterpret_cast<uint32_t*>(&l);
}

// ---------------------------------------------------------------------------
// 1) Degree counting: float RED atomics (measured ~3us)
// ---------------------------------------------------------------------------
__global__ void deg_kernel(const int* __restrict__ src, const int* __restrict__ dst) {
    int e = blockIdx.x * blockDim.x + threadIdx.x;
    if (e < N_EDGES) {
        atomicAdd(&g_degout[src[e]], 1.0f);
        atomicAdd(&g_degin[dst[e]], 1.0f);
    }
}

// ---------------------------------------------------------------------------
// 2) Block-local scan of degin (49 blocks x 1024) + B tile prep (first 4096)
// ---------------------------------------------------------------------------
__global__ __launch_bounds__(1024) void scan1_kernel(const float* __restrict__ fc_w,
                                                     const float* __restrict__ res_w) {
    __shared__ int sh[1024];
    const int t = threadIdx.x, b = blockIdx.x;
    const int node = b * 1024 + t;
    int v = (node < N_NODES) ? (int)g_degin[node] : 0;
    sh[t] = v;
    __syncthreads();
#pragma unroll
    for (int off = 1; off < 1024; off <<= 1) {
        int u = (t >= off) ? sh[t - off] : 0;
        __syncthreads();
        sh[t] += u;
        __syncthreads();
    }
    if (node < N_NODES) g_part[node] = sh[t] - v;   // exclusive within block
    if (t == 1023) g_bsum[b] = sh[1023];

    // B-prep on first 4096 global threads (independent of scan)
    if (node < 4096) {
        int h  = node >> 11;
        int rem = node & 2047;
        int n  = rem >> 4;
        int kb = (rem & 15) * 8;
        const float* W = h ? res_w : fc_w;
        uint32_t hp[4], lp[4];
#pragma unroll
        for (int j = 0; j < 4; j++) {
            uint16_t h0, l0, h1, l1;
            split_bf16(W[(kb + 2 * j)     * DIM + n], h0, l0);
            split_bf16(W[(kb + 2 * j + 1) * DIM + n], h1, l1);
            hp[j] = ((uint32_t)h1 << 16) | h0;
            lp[j] = ((uint32_t)l1 << 16) | l0;
        }
        uint32_t off = (uint32_t)(n * 256 + kb * 2);
        *reinterpret_cast<uint4*>(&g_Bt[(uint32_t)(h * 2)     * 32768u + off]) =
            make_uint4(hp[0], hp[1], hp[2], hp[3]);
        *reinterpret_cast<uint4*>(&g_Bt[(uint32_t)(h * 2 + 1) * 32768u + off]) =
            make_uint4(lp[0], lp[1], lp[2], lp[3]);
    }
}

// ---------------------------------------------------------------------------
// 3) Add-back + norms: base from 49 block sums, write off/cursor/norms
// ---------------------------------------------------------------------------
__global__ __launch_bounds__(1024) void scan2_kernel() {
    __shared__ int bs[64];
    const int t = threadIdx.x, b = blockIdx.x;
    if (t < 64) bs[t] = (t < SCAN_BLOCKS) ? g_bsum[t] : 0;
    __syncthreads();
    int base = 0;
#pragma unroll
    for (int i = 0; i < SCAN_BLOCKS; i++) base += (i < b) ? bs[i] : 0;
    const int node = b * 1024 + t;
    if (node < N_NODES) {
        int off = base + g_part[node];
        g_off[node] = off;
        g_cursor[node] = off;
        g_outnorm[node] = rsqrtf(fmaxf(g_degout[node], 1.0f));
        g_innorm[node]  = rsqrtf(fmaxf(g_degin[node], 1.0f));
    }
    if (b == SCAN_BLOCKS - 1 && t == 1023) g_off[N_NODES] = N_EDGES;
}

// ---------------------------------------------------------------------------
// 4) Scatter (PROFILED): 4 edges per thread -> 4 return-atomics in flight
// ---------------------------------------------------------------------------
__global__ void scatter_kernel(const int* __restrict__ src, const int* __restrict__ dst) {
    int i = blockIdx.x * blockDim.x + threadIdx.x;     // 150000 items
    if (i < N_EDGES / 4) {
        int4 d4 = reinterpret_cast<const int4*>(dst)[i];
        int4 s4 = reinterpret_cast<const int4*>(src)[i];
        int p0 = atomicAdd(&g_cursor[d4.x], 1);
        int p1 = atomicAdd(&g_cursor[d4.y], 1);
        int p2 = atomicAdd(&g_cursor[d4.z], 1);
        int p3 = atomicAdd(&g_cursor[d4.w], 1);
        g_ssrc[p0] = s4.x;
        g_ssrc[p1] = s4.y;
        g_ssrc[p2] = s4.z;
        g_ssrc[p3] = s4.w;
    }
}

// ---------------------------------------------------------------------------
// 5) CSR aggregation (measured 27us): one warp per node, MLP=8
// ---------------------------------------------------------------------------
__global__ __launch_bounds__(256) void agg_kernel(const float* __restrict__ feat) {
    const int warp = blockIdx.x * (blockDim.x >> 5) + (threadIdx.x >> 5);
    const int lane = threadIdx.x & 31;
    if (warp >= N_NODES) return;
    const int beg = g_off[warp];
    const int end = g_off[warp + 1];
    const float4* f4 = reinterpret_cast<const float4*>(feat);

    float4 a0 = make_float4(0.f, 0.f, 0.f, 0.f);
    float4 a1 = make_float4(0.f, 0.f, 0.f, 0.f);

    int e = beg;
    for (; e + 8 <= end; e += 8) {
        int s[8];
#pragma unroll
        for (int j = 0; j < 8; j++) s[j] = __ldg(&g_ssrc[e + j]);
        float on[8];
#pragma unroll
        for (int j = 0; j < 8; j++) on[j] = __ldg(&g_outnorm[s[j]]);
        float4 v[8];
#pragma unroll
        for (int j = 0; j < 8; j++) v[j] = f4[(size_t)s[j] * 32 + lane];
#pragma unroll
        for (int j = 0; j < 8; j += 2) {
            a0.x = fmaf(v[j].x, on[j], a0.x);
            a0.y = fmaf(v[j].y, on[j], a0.y);
            a0.z = fmaf(v[j].z, on[j], a0.z);
            a0.w = fmaf(v[j].w, on[j], a0.w);
            a1.x = fmaf(v[j + 1].x, on[j + 1], a1.x);
            a1.y = fmaf(v[j + 1].y, on[j + 1], a1.y);
            a1.z = fmaf(v[j + 1].z, on[j + 1], a1.z);
            a1.w = fmaf(v[j + 1].w, on[j + 1], a1.w);
        }
    }
    if (e + 4 <= end) {
        int s[4];
#pragma unroll
        for (int j = 0; j < 4; j++) s[j] = __ldg(&g_ssrc[e + j]);
        float on[4];
#pragma unroll
        for (int j = 0; j < 4; j++) on[j] = __ldg(&g_outnorm[s[j]]);
        float4 v[4];
#pragma unroll
        for (int j = 0; j < 4; j++) v[j] = f4[(size_t)s[j] * 32 + lane];
#pragma unroll
        for (int j = 0; j < 4; j += 2) {
            a0.x = fmaf(v[j].x, on[j], a0.x);
            a0.y = fmaf(v[j].y, on[j], a0.y);
            a0.z = fmaf(v[j].z, on[j], a0.z);
            a0.w = fmaf(v[j].w, on[j], a0.w);
            a1.x = fmaf(v[j + 1].x, on[j + 1], a1.x);
            a1.y = fmaf(v[j + 1].y, on[j + 1], a1.y);
            a1.z = fmaf(v[j + 1].z, on[j + 1], a1.z);
            a1.w = fmaf(v[j + 1].w, on[j + 1], a1.w);
        }
        e += 4;
    }
    for (; e < end; e++) {
        int s0 = __ldg(&g_ssrc[e]);
        float on = __ldg(&g_outnorm[s0]);
        float4 v = f4[(size_t)s0 * 32 + lane];
        a0.x = fmaf(v.x, on, a0.x);
        a0.y = fmaf(v.y, on, a0.y);
        a0.z = fmaf(v.z, on, a0.z);
        a0.w = fmaf(v.w, on, a0.w);
    }
    a0.x += a1.x; a0.y += a1.y; a0.z += a1.z; a0.w += a1.w;
    reinterpret_cast<float4*>(g_agg)[(size_t)warp * 32 + lane] = a0;
}

// ---------------------------------------------------------------------------
// 6) Persistent mma.sync bf16 GEMM + bias + LayerNorm + ReLU (R10 version)
// ---------------------------------------------------------------------------
#define ROW_BYTES 272
#define TILE_BYTES (128 * ROW_BYTES)
#define SMEM_B     0
#define SMEM_A_HI  (4 * TILE_BYTES)
#define SMEM_A_LO  (SMEM_A_HI + TILE_BYTES)
#define SMEM_STATS (SMEM_A_LO + TILE_BYTES)
#define SMEM_TOTAL (SMEM_STATS + 4096)

__device__ __forceinline__ uint32_t smem_u32(const void* p) {
    uint32_t a;
    asm("{ .reg .u64 t; cvta.to.shared.u64 t, %1; cvt.u32.u64 %0, t; }"
        : "=r"(a) : "l"(p));
    return a;
}
__device__ __forceinline__ void ldsm4(uint32_t (&r)[4], uint32_t addr) {
    asm volatile("ldmatrix.sync.aligned.m8n8.x4.shared.b16 {%0,%1,%2,%3}, [%4];"
                 : "=r"(r[0]), "=r"(r[1]), "=r"(r[2]), "=r"(r[3]) : "r"(addr));
}
__device__ __forceinline__ void mma16816(float (&d)[4], const uint32_t (&a)[4],
                                         uint32_t b0, uint32_t b1) {
    asm volatile("mma.sync.aligned.m16n8k16.row.col.f32.bf16.bf16.f32 "
                 "{%0,%1,%2,%3}, {%4,%5,%6,%7}, {%8,%9}, {%0,%1,%2,%3};"
                 : "+f"(d[0]), "+f"(d[1]), "+f"(d[2]), "+f"(d[3])
                 : "r"(a[0]), "r"(a[1]), "r"(a[2]), "r"(a[3]), "r"(b0), "r"(b1));
}
#define BAR_GRP(id) asm volatile("bar.sync %0, %1;" :: "r"((id) + 1), "r"(128) : "memory")

__global__ __launch_bounds__(512) void gemm_mma_kernel(
    const float* __restrict__ feat,
    const float* __restrict__ fc_b,
    const float* __restrict__ ln_g,
    const float* __restrict__ ln_b,
    float* __restrict__ out)
{
    extern __shared__ __align__(16) char smem[];
    const uint32_t sb = smem_u32(smem);
    const int tid  = threadIdx.x;
    const int wid  = tid >> 5;
    const int lane = tid & 31;
    const int wm   = wid & 3;
    const int wn   = wid >> 2;
    const int gt   = ((wid >> 2) << 5) | lane;

    {
        const uint4* src = reinterpret_cast<const uint4*>(g_Bt);
#pragma unroll
        for (int i = 0; i < 16; i++) {
            int idx = tid + i * 512;
            int t = idx >> 11, rem = idx & 2047;
            int n = rem >> 4, c = rem & 15;
            uint4 v = src[t * 2048 + n * 16 + c];
            *reinterpret_cast<uint4*>(smem + SMEM_B + t * TILE_BYTES + n * ROW_BYTES + c * 16) = v;
        }
    }
    __syncthreads();

    const uint32_t lane_off = (uint32_t)((lane & 15) * ROW_BYTES + (lane >> 4) * 16);
    const int r = lane >> 2, q = lane & 3;
    float2* stats = reinterpret_cast<float2*>(smem + SMEM_STATS);
    const int lr0 = gt >> 4;
    const int lkb = (gt & 15) * 8;

    for (int tile = blockIdx.x; tile < N_TILES; tile += gridDim.x) {
        const int bm0 = tile * 128;

        auto load_a_slice = [&](int half) {
            const float* Ap = half ? feat : g_agg;
#pragma unroll
            for (int pass = 0; pass < 4; pass++) {
                int row_l = wm * 32 + pass * 8 + lr0;
                int row_g = bm0 + row_l;
                float x[8];
                if (row_g < N_NODES) {
                    float4 v0 = *reinterpret_cast<const float4*>(Ap + (size_t)row_g * DIM + lkb);
                    float4 v1 = *reinterpret_cast<const float4*>(Ap + (size_t)row_g * DIM + lkb + 4);
                    x[0]=v0.x; x[1]=v0.y; x[2]=v0.z; x[3]=v0.w;
                    x[4]=v1.x; x[5]=v1.y; x[6]=v1.z; x[7]=v1.w;
                    if (half == 0) {
                        float s = g_innorm[row_g];
#pragma unroll
                        for (int j = 0; j < 8; j++) x[j] *= s;
                    }
                } else {
#pragma unroll
                    for (int j = 0; j < 8; j++) x[j] = 0.0f;
                }
                uint32_t hp[4], lp[4];
#pragma unroll
                for (int j = 0; j < 4; j++)
                    split2(x[2 * j], x[2 * j + 1], hp[j], lp[j]);
                uint32_t off = (uint32_t)(row_l * ROW_BYTES + lkb * 2);
                *reinterpret_cast<uint4*>(smem + SMEM_A_HI + off) = make_uint4(hp[0], hp[1], hp[2], hp[3]);
                *reinterpret_cast<uint4*>(smem + SMEM_A_LO + off) = make_uint4(lp[0], lp[1], lp[2], lp[3]);
            }
        };

        float acc[2][4][4];
#pragma unroll
        for (int m = 0; m < 2; m++)
#pragma unroll
            for (int n = 0; n < 4; n++)
#pragma unroll
                for (int c = 0; c < 4; c++) acc[m][n][c] = 0.0f;

        auto compute_half = [&](int half) {
            const uint32_t bhi0 = sb + SMEM_B + (uint32_t)(half * 2) * TILE_BYTES
                                + (uint32_t)(wn * 32) * ROW_BYTES;
            const uint32_t blo0 = bhi0 + TILE_BYTES;
            const uint32_t ahi0 = sb + SMEM_A_HI + (uint32_t)(wm * 32) * ROW_BYTES;
            const uint32_t alo0 = sb + SMEM_A_LO + (uint32_t)(wm * 32) * ROW_BYTES;
#pragma unroll 2
            for (int ks = 0; ks < 8; ks++) {
                const uint32_t koff = (uint32_t)(ks * 32) + lane_off;
                uint32_t ah[2][4], al[2][4], bh[2][4], bl[2][4];
                ldsm4(ah[0], ahi0 + koff);
                ldsm4(ah[1], ahi0 + 16 * ROW_BYTES + koff);
                ldsm4(al[0], alo0 + koff);
                ldsm4(al[1], alo0 + 16 * ROW_BYTES + koff);
                ldsm4(bh[0], bhi0 + koff);
                ldsm4(bh[1], bhi0 + 16 * ROW_BYTES + koff);
                ldsm4(bl[0], blo0 + koff);
                ldsm4(bl[1], blo0 + 16 * ROW_BYTES + koff);
#pragma unroll
                for (int ng = 0; ng < 2; ng++)
#pragma unroll
                    for (int m = 0; m < 2; m++) {
                        mma16816(acc[m][2 * ng],     ah[m], bh[ng][0], bh[ng][2]);
                        mma16816(acc[m][2 * ng + 1], ah[m], bh[ng][1], bh[ng][3]);
                    }
#pragma unroll
                for (int ng = 0; ng < 2; ng++)
#pragma unroll
                    for (int m = 0; m < 2; m++) {
                        mma16816(acc[m][2 * ng],     ah[m], bl[ng][0], bl[ng][2]);
                        mma16816(acc[m][2 * ng + 1], ah[m], bl[ng][1], bl[ng][3]);
                    }
#pragma unroll
                for (int ng = 0; ng < 2; ng++)
#pragma unroll
                    for (int m = 0; m < 2; m++) {
                        mma16816(acc[m][2 * ng],     al[m], bh[ng][0], bh[ng][2]);
                        mma16816(acc[m][2 * ng + 1], al[m], bh[ng][1], bh[ng][3]);
                    }
            }
        };

        load_a_slice(0);
        BAR_GRP(wm);
        compute_half(0);
        BAR_GRP(wm);
        load_a_slice(1);
        BAR_GRP(wm);
        compute_half(1);

        int rowl[4];
        float innm[4];
#pragma unroll
        for (int mf = 0; mf < 2; mf++)
#pragma unroll
            for (int s = 0; s < 2; s++) {
                int i = mf * 2 + s;
                rowl[i] = wm * 32 + mf * 16 + s * 8 + r;
                int row_g = bm0 + rowl[i];
                innm[i] = (row_g < N_NODES) ? g_innorm[row_g] : 0.0f;
            }

        float s1[4] = {0.f, 0.f, 0.f, 0.f}, s2[4] = {0.f, 0.f, 0.f, 0.f};
#pragma unroll
        for (int nf = 0; nf < 4; nf++) {
            int col = wn * 32 + nf * 8 + q * 2;
            float2 bs = *reinterpret_cast<const float2*>(fc_b + col);
#pragma unroll
            for (int mf = 0; mf < 2; mf++)
#pragma unroll
                for (int s = 0; s < 2; s++) {
                    int i = mf * 2 + s;
                    float x = acc[mf][nf][s * 2]     + innm[i] * bs.x;
                    float y = acc[mf][nf][s * 2 + 1] + innm[i] * bs.y;
                    acc[mf][nf][s * 2] = x;
                    acc[mf][nf][s * 2 + 1] = y;
                    s1[i] += x + y;
                    s2[i] += x * x + y * y;
                }
        }
#pragma unroll
        for (int o = 1; o <= 2; o <<= 1)
#pragma unroll
            for (int i = 0; i < 4; i++) {
                s1[i] += __shfl_xor_sync(0xFFFFFFFFu, s1[i], o);
                s2[i] += __shfl_xor_sync(0xFFFFFFFFu, s2[i], o);
            }

        if (q == 0) {
#pragma unroll
            for (int i = 0; i < 4; i++)
                stats[rowl[i] * 4 + wn] = make_float2(s1[i], s2[i]);
        }
        BAR_GRP(wm);

        float mu[4], inv[4];
#pragma unroll
        for (int i = 0; i < 4; i++) {
            float2 a0 = stats[rowl[i] * 4 + 0];
            float2 a1 = stats[rowl[i] * 4 + 1];
            float2 a2 = stats[rowl[i] * 4 + 2];
            float2 a3 = stats[rowl[i] * 4 + 3];
            float S = a0.x + a1.x + a2.x + a3.x;
            float S2 = a0.y + a1.y + a2.y + a3.y;
            mu[i] = S * (1.0f / DIM);
            float var = S2 * (1.0f / DIM) - mu[i] * mu[i];
            inv[i] = rsqrtf(var + LN_EPS);
        }

#pragma unroll
        for (int nf = 0; nf < 4; nf++) {
            int col = wn * 32 + nf * 8 + q * 2;
            float2 g2 = *reinterpret_cast<const float2*>(ln_g + col);
            float2 b2 = *reinterpret_cast<const float2*>(ln_b + col);
#pragma unroll
            for (int mf = 0; mf < 2; mf++)
#pragma unroll
                for (int s = 0; s < 2; s++) {
                    int i = mf * 2 + s;
                    int row_g = bm0 + rowl[i];
                    if (row_g < N_NODES) {
                        float2 o;
                        o.x = fmaxf((acc[mf][nf][s * 2]     - mu[i]) * inv[i] * g2.x + b2.x, 0.f);
                        o.y = fmaxf((acc[mf][nf][s * 2 + 1] - mu[i]) * inv[i] * g2.y + b2.y, 0.f);
                        *reinterpret_cast<float2*>(out + (size_t)row_g * DIM + col) = o;
                    }
                }
        }
        BAR_GRP(wm);
    }
}

// ---------------------------------------------------------------------------
extern "C" void kernel_launch(void* const* d_in, const int* in_sizes, int n_in,
                              void* d_out, int out_size) {
    const float* feat  = (const float*)d_in[0];
    const int*   src   = (const int*)d_in[1];
    const int*   dst   = (const int*)d_in[2];
    const float* fc_w  = (const float*)d_in[3];
    const float* fc_b  = (const float*)d_in[4];
    const float* res_w = (const float*)d_in[5];
    const float* ln_g  = (const float*)d_in[6];
    const float* ln_b  = (const float*)d_in[7];
    float* out = (float*)d_out;

    void *dout_p, *din_p;
    cudaGetSymbolAddress(&dout_p, g_degout);
    cudaGetSymbolAddress(&din_p, g_degin);
    cudaMemsetAsync(dout_p, 0, sizeof(float) * N_NODES);
    cudaMemsetAsync(din_p, 0, sizeof(float) * N_NODES);

    // launch order: scatter is kernel #4 (the one ncu profiles)
    deg_kernel<<<(N_EDGES + 255) / 256, 256>>>(src, dst);
    scan1_kernel<<<SCAN_BLOCKS, 1024>>>(fc_w, res_w);
    scan2_kernel<<<SCAN_BLOCKS, 1024>>>();
    scatter_kernel<<<(N_EDGES / 4 + 255) / 256, 256>>>(src, dst);
    agg_kernel<<<(N_NODES * 32 + 255) / 256, 256>>>(feat);

    cudaFuncSetAttribute(gemm_mma_kernel,
                         cudaFuncAttributeMaxDynamicSharedMemorySize, SMEM_TOTAL);
    gemm_mma_kernel<<<148, 512, SMEM_TOTAL>>>(feat, fc_b, ln_g, ln_b, out);
}

// round 14
// speedup vs baseline: 1.0189x; 1.0189x over previous
#include <cuda_runtime.h>
#include <cuda_bf16.h>
#include <cstdint>

#define N_NODES 50000
#define N_EDGES 600000
#define DIM     128
#define LN_EPS  1e-5f
#define N_TILES ((N_NODES + 127) / 128)   // 391
#define SCAN_BLOCKS 49                    // 49 * 1024 >= 50000

// ---------------------------------------------------------------------------
// Scratch (device globals: allocation-free per harness rules)
// ---------------------------------------------------------------------------
__device__ float g_agg[N_NODES * DIM];
__device__ float g_degout[N_NODES];
__device__ int   g_degin_i[N_NODES];
__device__ float g_outnorm[N_NODES];
__device__ float g_innorm[N_NODES];
__device__ int   g_rank[N_EDGES];
__device__ int   g_part[N_NODES];
__device__ int   g_bsum[64];
__device__ int   g_off[N_NODES + 1];
__device__ int   g_ssrc[N_EDGES];
// B tiles (bf16, plain [n][k] layout): [h0_hi | h0_lo | h1_hi | h1_lo]
__device__ __align__(16) uint8_t g_Bt[4 * 32768];

// ---------------------------------------------------------------------------
// bf16 hi/lo split helpers
// ---------------------------------------------------------------------------
__device__ __forceinline__ void split_bf16(float x, uint16_t& hi, uint16_t& lo) {
    __nv_bfloat16 h = __float2bfloat16(x);
    hi = __bfloat16_as_ushort(h);
    float hf = __uint_as_float((uint32_t)hi << 16);
    lo = __bfloat16_as_ushort(__float2bfloat16(x - hf));
}
__device__ __forceinline__ void split2(float x0, float x1, uint32_t& hi2, uint32_t& lo2) {
    __nv_bfloat162 h = __floats2bfloat162_rn(x0, x1);
    hi2 = *reinterpret_cast<uint32_t*>(&h);
    float hf0 = __uint_as_float(hi2 << 16);
    float hf1 = __uint_as_float(hi2 & 0xFFFF0000u);
    __nv_bfloat162 l = __floats2bfloat162_rn(x0 - hf0, x1 - hf1);
    lo2 = *reinterpret_cast<uint32_t*>(&l);
}

// ---------------------------------------------------------------------------
// 1) Degree counting + bucket rank: indeg atomic RETURNS this edge's rank
//    within its dst bucket -> later scatter needs no atomics at all.
// ---------------------------------------------------------------------------
__global__ void deg_kernel(const int* __restrict__ src, const int* __restrict__ dst) {
    int e = blockIdx.x * blockDim.x + threadIdx.x;
    if (e < N_EDGES) {
        atomicAdd(&g_degout[src[e]], 1.0f);
        g_rank[e] = atomicAdd(&g_degin_i[dst[e]], 1);
    }
}

// ---------------------------------------------------------------------------
// 2) Block-local scan of degin (49 blocks x 1024) + B tile prep (first 4096)
// ---------------------------------------------------------------------------
__global__ __launch_bounds__(1024) void scan1_kernel(const float* __restrict__ fc_w,
                                                     const float* __restrict__ res_w) {
    __shared__ int sh[1024];
    const int t = threadIdx.x, b = blockIdx.x;
    const int node = b * 1024 + t;
    int v = (node < N_NODES) ? g_degin_i[node] : 0;
    sh[t] = v;
    __syncthreads();
#pragma unroll
    for (int off = 1; off < 1024; off <<= 1) {
        int u = (t >= off) ? sh[t - off] : 0;
        __syncthreads();
        sh[t] += u;
        __syncthreads();
    }
    if (node < N_NODES) g_part[node] = sh[t] - v;   // exclusive within block
    if (t == 1023) g_bsum[b] = sh[1023];

    if (node < 4096) {
        int h  = node >> 11;
        int rem = node & 2047;
        int n  = rem >> 4;
        int kb = (rem & 15) * 8;
        const float* W = h ? res_w : fc_w;
        uint32_t hp[4], lp[4];
#pragma unroll
        for (int j = 0; j < 4; j++) {
            uint16_t h0, l0, h1, l1;
            split_bf16(W[(kb + 2 * j)     * DIM + n], h0, l0);
            split_bf16(W[(kb + 2 * j + 1) * DIM + n], h1, l1);
            hp[j] = ((uint32_t)h1 << 16) | h0;
            lp[j] = ((uint32_t)l1 << 16) | l0;
        }
        uint32_t off = (uint32_t)(n * 256 + kb * 2);
        *reinterpret_cast<uint4*>(&g_Bt[(uint32_t)(h * 2)     * 32768u + off]) =
            make_uint4(hp[0], hp[1], hp[2], hp[3]);
        *reinterpret_cast<uint4*>(&g_Bt[(uint32_t)(h * 2 + 1) * 32768u + off]) =
            make_uint4(lp[0], lp[1], lp[2], lp[3]);
    }
}

// ---------------------------------------------------------------------------
// 3) Add-back + norms
// ---------------------------------------------------------------------------
__global__ __launch_bounds__(1024) void scan2_kernel() {
    __shared__ int bs[64];
    const int t = threadIdx.x, b = blockIdx.x;
    if (t < 64) bs[t] = (t < SCAN_BLOCKS) ? g_bsum[t] : 0;
    __syncthreads();
    int base = 0;
#pragma unroll
    for (int i = 0; i < SCAN_BLOCKS; i++) base += (i < b) ? bs[i] : 0;
    const int node = b * 1024 + t;
    if (node < N_NODES) {
        g_off[node] = base + g_part[node];
        g_outnorm[node] = rsqrtf(fmaxf(g_degout[node], 1.0f));
        g_innorm[node]  = rsqrtf(fmaxf((float)g_degin_i[node], 1.0f));
    }
    if (b == SCAN_BLOCKS - 1 && t == 1023) g_off[N_NODES] = N_EDGES;
}

// ---------------------------------------------------------------------------
// 4) Scatter (PROFILED): NO atomics — pos = off[dst] + rank. 4 edges/thread.
// ---------------------------------------------------------------------------
__global__ void scatter_kernel(const int* __restrict__ src, const int* __restrict__ dst) {
    int i = blockIdx.x * blockDim.x + threadIdx.x;     // 150000 items
    if (i < N_EDGES / 4) {
        int4 d4 = reinterpret_cast<const int4*>(dst)[i];
        int4 s4 = reinterpret_cast<const int4*>(src)[i];
        int4 r4 = reinterpret_cast<const int4*>(g_rank)[i];
        g_ssrc[__ldg(&g_off[d4.x]) + r4.x] = s4.x;
        g_ssrc[__ldg(&g_off[d4.y]) + r4.y] = s4.y;
        g_ssrc[__ldg(&g_off[d4.z]) + r4.z] = s4.z;
        g_ssrc[__ldg(&g_off[d4.w]) + r4.w] = s4.w;
    }
}

// ---------------------------------------------------------------------------
// 5) CSR aggregation (measured 27us): one warp per node, MLP=8
// ---------------------------------------------------------------------------
__global__ __launch_bounds__(256) void agg_kernel(const float* __restrict__ feat) {
    const int warp = blockIdx.x * (blockDim.x >> 5) + (threadIdx.x >> 5);
    const int lane = threadIdx.x & 31;
    if (warp >= N_NODES) return;
    const int beg = g_off[warp];
    const int end = g_off[warp + 1];
    const float4* f4 = reinterpret_cast<const float4*>(feat);

    float4 a0 = make_float4(0.f, 0.f, 0.f, 0.f);
    float4 a1 = make_float4(0.f, 0.f, 0.f, 0.f);

    int e = beg;
    for (; e + 8 <= end; e += 8) {
        int s[8];
#pragma unroll
        for (int j = 0; j < 8; j++) s[j] = __ldg(&g_ssrc[e + j]);
        float on[8];
#pragma unroll
        for (int j = 0; j < 8; j++) on[j] = __ldg(&g_outnorm[s[j]]);
        float4 v[8];
#pragma unroll
        for (int j = 0; j < 8; j++) v[j] = f4[(size_t)s[j] * 32 + lane];
#pragma unroll
        for (int j = 0; j < 8; j += 2) {
            a0.x = fmaf(v[j].x, on[j], a0.x);
            a0.y = fmaf(v[j].y, on[j], a0.y);
            a0.z = fmaf(v[j].z, on[j], a0.z);
            a0.w = fmaf(v[j].w, on[j], a0.w);
            a1.x = fmaf(v[j + 1].x, on[j + 1], a1.x);
            a1.y = fmaf(v[j + 1].y, on[j + 1], a1.y);
            a1.z = fmaf(v[j + 1].z, on[j + 1], a1.z);
            a1.w = fmaf(v[j + 1].w, on[j + 1], a1.w);
        }
    }
    if (e + 4 <= end) {
        int s[4];
#pragma unroll
        for (int j = 0; j < 4; j++) s[j] = __ldg(&g_ssrc[e + j]);
        float on[4];
#pragma unroll
        for (int j = 0; j < 4; j++) on[j] = __ldg(&g_outnorm[s[j]]);
        float4 v[4];
#pragma unroll
        for (int j = 0; j < 4; j++) v[j] = f4[(size_t)s[j] * 32 + lane];
#pragma unroll
        for (int j = 0; j < 4; j += 2) {
            a0.x = fmaf(v[j].x, on[j], a0.x);
            a0.y = fmaf(v[j].y, on[j], a0.y);
            a0.z = fmaf(v[j].z, on[j], a0.z);
            a0.w = fmaf(v[j].w, on[j], a0.w);
            a1.x = fmaf(v[j + 1].x, on[j + 1], a1.x);
            a1.y = fmaf(v[j + 1].y, on[j + 1], a1.y);
            a1.z = fmaf(v[j + 1].z, on[j + 1], a1.z);
            a1.w = fmaf(v[j + 1].w, on[j + 1], a1.w);
        }
        e += 4;
    }
    for (; e < end; e++) {
        int s0 = __ldg(&g_ssrc[e]);
        float on = __ldg(&g_outnorm[s0]);
        float4 v = f4[(size_t)s0 * 32 + lane];
        a0.x = fmaf(v.x, on, a0.x);
        a0.y = fmaf(v.y, on, a0.y);
        a0.z = fmaf(v.z, on, a0.z);
        a0.w = fmaf(v.w, on, a0.w);
    }
    a0.x += a1.x; a0.y += a1.y; a0.z += a1.z; a0.w += a1.w;
    reinterpret_cast<float4*>(g_agg)[(size_t)warp * 32 + lane] = a0;
}

// ---------------------------------------------------------------------------
// 6) Persistent mma.sync bf16 GEMM + bias + LayerNorm + ReLU (R10 version)
// ---------------------------------------------------------------------------
#define ROW_BYTES 272
#define TILE_BYTES (128 * ROW_BYTES)
#define SMEM_B     0
#define SMEM_A_HI  (4 * TILE_BYTES)
#define SMEM_A_LO  (SMEM_A_HI + TILE_BYTES)
#define SMEM_STATS (SMEM_A_LO + TILE_BYTES)
#define SMEM_TOTAL (SMEM_STATS + 4096)

__device__ __forceinline__ uint32_t smem_u32(const void* p) {
    uint32_t a;
    asm("{ .reg .u64 t; cvta.to.shared.u64 t, %1; cvt.u32.u64 %0, t; }"
        : "=r"(a) : "l"(p));
    return a;
}
__device__ __forceinline__ void ldsm4(uint32_t (&r)[4], uint32_t addr) {
    asm volatile("ldmatrix.sync.aligned.m8n8.x4.shared.b16 {%0,%1,%2,%3}, [%4];"
                 : "=r"(r[0]), "=r"(r[1]), "=r"(r[2]), "=r"(r[3]) : "r"(addr));
}
__device__ __forceinline__ void mma16816(float (&d)[4], const uint32_t (&a)[4],
                                         uint32_t b0, uint32_t b1) {
    asm volatile("mma.sync.aligned.m16n8k16.row.col.f32.bf16.bf16.f32 "
                 "{%0,%1,%2,%3}, {%4,%5,%6,%7}, {%8,%9}, {%0,%1,%2,%3};"
                 : "+f"(d[0]), "+f"(d[1]), "+f"(d[2]), "+f"(d[3])
                 : "r"(a[0]), "r"(a[1]), "r"(a[2]), "r"(a[3]), "r"(b0), "r"(b1));
}
#define BAR_GRP(id) asm volatile("bar.sync %0, %1;" :: "r"((id) + 1), "r"(128) : "memory")

__global__ __launch_bounds__(512) void gemm_mma_kernel(
    const float* __restrict__ feat,
    const float* __restrict__ fc_b,
    const float* __restrict__ ln_g,
    const float* __restrict__ ln_b,
    float* __restrict__ out)
{
    extern __shared__ __align__(16) char smem[];
    const uint32_t sb = smem_u32(smem);
    const int tid  = threadIdx.x;
    const int wid  = tid >> 5;
    const int lane = tid & 31;
    const int wm   = wid & 3;
    const int wn   = wid >> 2;
    const int gt   = ((wid >> 2) << 5) | lane;

    {
        const uint4* src = reinterpret_cast<const uint4*>(g_Bt);
#pragma unroll
        for (int i = 0; i < 16; i++) {
            int idx = tid + i * 512;
            int t = idx >> 11, rem = idx & 2047;
            int n = rem >> 4, c = rem & 15;
            uint4 v = src[t * 2048 + n * 16 + c];
            *reinterpret_cast<uint4*>(smem + SMEM_B + t * TILE_BYTES + n * ROW_BYTES + c * 16) = v;
        }
    }
    __syncthreads();

    const uint32_t lane_off = (uint32_t)((lane & 15) * ROW_BYTES + (lane >> 4) * 16);
    const int r = lane >> 2, q = lane & 3;
    float2* stats = reinterpret_cast<float2*>(smem + SMEM_STATS);
    const int lr0 = gt >> 4;
    const int lkb = (gt & 15) * 8;

    for (int tile = blockIdx.x; tile < N_TILES; tile += gridDim.x) {
        const int bm0 = tile * 128;

        auto load_a_slice = [&](int half) {
            const float* Ap = half ? feat : g_agg;
#pragma unroll
            for (int pass = 0; pass < 4; pass++) {
                int row_l = wm * 32 + pass * 8 + lr0;
                int row_g = bm0 + row_l;
                float x[8];
                if (row_g < N_NODES) {
                    float4 v0 = *reinterpret_cast<const float4*>(Ap + (size_t)row_g * DIM + lkb);
                    float4 v1 = *reinterpret_cast<const float4*>(Ap + (size_t)row_g * DIM + lkb + 4);
                    x[0]=v0.x; x[1]=v0.y; x[2]=v0.z; x[3]=v0.w;
                    x[4]=v1.x; x[5]=v1.y; x[6]=v1.z; x[7]=v1.w;
                    if (half == 0) {
                        float s = g_innorm[row_g];
#pragma unroll
                        for (int j = 0; j < 8; j++) x[j] *= s;
                    }
                } else {
#pragma unroll
                    for (int j = 0; j < 8; j++) x[j] = 0.0f;
                }
                uint32_t hp[4], lp[4];
#pragma unroll
                for (int j = 0; j < 4; j++)
                    split2(x[2 * j], x[2 * j + 1], hp[j], lp[j]);
                uint32_t off = (uint32_t)(row_l * ROW_BYTES + lkb * 2);
                *reinterpret_cast<uint4*>(smem + SMEM_A_HI + off) = make_uint4(hp[0], hp[1], hp[2], hp[3]);
                *reinterpret_cast<uint4*>(smem + SMEM_A_LO + off) = make_uint4(lp[0], lp[1], lp[2], lp[3]);
            }
        };

        float acc[2][4][4];
#pragma unroll
        for (int m = 0; m < 2; m++)
#pragma unroll
            for (int n = 0; n < 4; n++)
#pragma unroll
                for (int c = 0; c < 4; c++) acc[m][n][c] = 0.0f;

        auto compute_half = [&](int half) {
            const uint32_t bhi0 = sb + SMEM_B + (uint32_t)(half * 2) * TILE_BYTES
                                + (uint32_t)(wn * 32) * ROW_BYTES;
            const uint32_t blo0 = bhi0 + TILE_BYTES;
            const uint32_t ahi0 = sb + SMEM_A_HI + (uint32_t)(wm * 32) * ROW_BYTES;
            const uint32_t alo0 = sb + SMEM_A_LO + (uint32_t)(wm * 32) * ROW_BYTES;
#pragma unroll 2
            for (int ks = 0; ks < 8; ks++) {
                const uint32_t koff = (uint32_t)(ks * 32) + lane_off;
                uint32_t ah[2][4], al[2][4], bh[2][4], bl[2][4];
                ldsm4(ah[0], ahi0 + koff);
                ldsm4(ah[1], ahi0 + 16 * ROW_BYTES + koff);
                ldsm4(al[0], alo0 + koff);
                ldsm4(al[1], alo0 + 16 * ROW_BYTES + koff);
                ldsm4(bh[0], bhi0 + koff);
                ldsm4(bh[1], bhi0 + 16 * ROW_BYTES + koff);
                ldsm4(bl[0], blo0 + koff);
                ldsm4(bl[1], blo0 + 16 * ROW_BYTES + koff);
#pragma unroll
                for (int ng = 0; ng < 2; ng++)
#pragma unroll
                    for (int m = 0; m < 2; m++) {
                        mma16816(acc[m][2 * ng],     ah[m], bh[ng][0], bh[ng][2]);
                        mma16816(acc[m][2 * ng + 1], ah[m], bh[ng][1], bh[ng][3]);
                    }
#pragma unroll
                for (int ng = 0; ng < 2; ng++)
#pragma unroll
                    for (int m = 0; m < 2; m++) {
                        mma16816(acc[m][2 * ng],     ah[m], bl[ng][0], bl[ng][2]);
                        mma16816(acc[m][2 * ng + 1], ah[m], bl[ng][1], bl[ng][3]);
                    }
#pragma unroll
                for (int ng = 0; ng < 2; ng++)
#pragma unroll
                    for (int m = 0; m < 2; m++) {
                        mma16816(acc[m][2 * ng],     al[m], bh[ng][0], bh[ng][2]);
                        mma16816(acc[m][2 * ng + 1], al[m], bh[ng][1], bh[ng][3]);
                    }
            }
        };

        load_a_slice(0);
        BAR_GRP(wm);
        compute_half(0);
        BAR_GRP(wm);
        load_a_slice(1);
        BAR_GRP(wm);
        compute_half(1);

        int rowl[4];
        float innm[4];
#pragma unroll
        for (int mf = 0; mf < 2; mf++)
#pragma unroll
            for (int s = 0; s < 2; s++) {
                int i = mf * 2 + s;
                rowl[i] = wm * 32 + mf * 16 + s * 8 + r;
                int row_g = bm0 + rowl[i];
                innm[i] = (row_g < N_NODES) ? g_innorm[row_g] : 0.0f;
            }

        float s1[4] = {0.f, 0.f, 0.f, 0.f}, s2[4] = {0.f, 0.f, 0.f, 0.f};
#pragma unroll
        for (int nf = 0; nf < 4; nf++) {
            int col = wn * 32 + nf * 8 + q * 2;
            float2 bs = *reinterpret_cast<const float2*>(fc_b + col);
#pragma unroll
            for (int mf = 0; mf < 2; mf++)
#pragma unroll
                for (int s = 0; s < 2; s++) {
                    int i = mf * 2 + s;
                    float x = acc[mf][nf][s * 2]     + innm[i] * bs.x;
                    float y = acc[mf][nf][s * 2 + 1] + innm[i] * bs.y;
                    acc[mf][nf][s * 2] = x;
                    acc[mf][nf][s * 2 + 1] = y;
                    s1[i] += x + y;
                    s2[i] += x * x + y * y;
                }
        }
#pragma unroll
        for (int o = 1; o <= 2; o <<= 1)
#pragma unroll
            for (int i = 0; i < 4; i++) {
                s1[i] += __shfl_xor_sync(0xFFFFFFFFu, s1[i], o);
                s2[i] += __shfl_xor_sync(0xFFFFFFFFu, s2[i], o);
            }

        if (q == 0) {
#pragma unroll
            for (int i = 0; i < 4; i++)
                stats[rowl[i] * 4 + wn] = make_float2(s1[i], s2[i]);
        }
        BAR_GRP(wm);

        float mu[4], inv[4];
#pragma unroll
        for (int i = 0; i < 4; i++) {
            float2 a0 = stats[rowl[i] * 4 + 0];
            float2 a1 = stats[rowl[i] * 4 + 1];
            float2 a2 = stats[rowl[i] * 4 + 2];
            float2 a3 = stats[rowl[i] * 4 + 3];
            float S = a0.x + a1.x + a2.x + a3.x;
            float S2 = a0.y + a1.y + a2.y + a3.y;
            mu[i] = S * (1.0f / DIM);
            float var = S2 * (1.0f / DIM) - mu[i] * mu[i];
            inv[i] = rsqrtf(var + LN_EPS);
        }

#pragma unroll
        for (int nf = 0; nf < 4; nf++) {
            int col = wn * 32 + nf * 8 + q * 2;
            float2 g2 = *reinterpret_cast<const float2*>(ln_g + col);
            float2 b2 = *reinterpret_cast<const float2*>(ln_b + col);
#pragma unroll
            for (int mf = 0; mf < 2; mf++)
#pragma unroll
                for (int s = 0; s < 2; s++) {
                    int i = mf * 2 + s;
                    int row_g = bm0 + rowl[i];
                    if (row_g < N_NODES) {
                        float2 o;
                        o.x = fmaxf((acc[mf][nf][s * 2]     - mu[i]) * inv[i] * g2.x + b2.x, 0.f);
                        o.y = fmaxf((acc[mf][nf][s * 2 + 1] - mu[i]) * inv[i] * g2.y + b2.y, 0.f);
                        *reinterpret_cast<float2*>(out + (size_t)row_g * DIM + col) = o;
                    }
                }
        }
        BAR_GRP(wm);
    }
}

// ---------------------------------------------------------------------------
extern "C" void kernel_launch(void* const* d_in, const int* in_sizes, int n_in,
                              void* d_out, int out_size) {
    const float* feat  = (const float*)d_in[0];
    const int*   src   = (const int*)d_in[1];
    const int*   dst   = (const int*)d_in[2];
    const float* fc_w  = (const float*)d_in[3];
    const float* fc_b  = (const float*)d_in[4];
    const float* res_w = (const float*)d_in[5];
    const float* ln_g  = (const float*)d_in[6];
    const float* ln_b  = (const float*)d_in[7];
    float* out = (float*)d_out;

    void *dout_p, *din_p;
    cudaGetSymbolAddress(&dout_p, g_degout);
    cudaGetSymbolAddress(&din_p, g_degin_i);
    cudaMemsetAsync(dout_p, 0, sizeof(float) * N_NODES);
    cudaMemsetAsync(din_p, 0, sizeof(int) * N_NODES);

    // launch order: scatter is kernel #4 (the one ncu profiles)
    deg_kernel<<<(N_EDGES + 255) / 256, 256>>>(src, dst);
    scan1_kernel<<<SCAN_BLOCKS, 1024>>>(fc_w, res_w);
    scan2_kernel<<<SCAN_BLOCKS, 1024>>>();
    scatter_kernel<<<(N_EDGES / 4 + 255) / 256, 256>>>(src, dst);
    agg_kernel<<<(N_NODES * 32 + 255) / 256, 256>>>(feat);

    cudaFuncSetAttribute(gemm_mma_kernel,
                         cudaFuncAttributeMaxDynamicSharedMemorySize, SMEM_TOTAL);
    gemm_mma_kernel<<<148, 512, SMEM_TOTAL>>>(feat, fc_b, ln_g, ln_b, out);
}

// round 15
// speedup vs baseline: 1.0192x; 1.0003x over previous
#include <cuda_runtime.h>
#include <cuda_bf16.h>
#include <cstdint>

#define N_NODES 50000
#define N_EDGES 600000
#define DIM     128
#define LN_EPS  1e-5f
#define N_TILES ((N_NODES + 127) / 128)   // 391
#define SCAN_BLOCKS 49                    // 49 * 1024 >= 50000

// ---------------------------------------------------------------------------
// Scratch (device globals: allocation-free per harness rules)
// ---------------------------------------------------------------------------
__device__ float g_agg[N_NODES * DIM];
__device__ float g_degout[N_NODES];
__device__ int   g_degin_i[N_NODES];
__device__ float g_outnorm[N_NODES];
__device__ float g_innorm[N_NODES];
__device__ int   g_rank[N_EDGES];
__device__ int   g_part[N_NODES];
__device__ int   g_bsum[64];
__device__ int   g_off[N_NODES + 1];
__device__ int   g_ssrc[N_EDGES];
// B tiles (bf16, plain [n][k] layout): [h0_hi | h0_lo | h1_hi | h1_lo]
__device__ __align__(16) uint8_t g_Bt[4 * 32768];

// ---------------------------------------------------------------------------
// bf16 hi/lo split helpers
// ---------------------------------------------------------------------------
__device__ __forceinline__ void split_bf16(float x, uint16_t& hi, uint16_t& lo) {
    __nv_bfloat16 h = __float2bfloat16(x);
    hi = __bfloat16_as_ushort(h);
    float hf = __uint_as_float((uint32_t)hi << 16);
    lo = __bfloat16_as_ushort(__float2bfloat16(x - hf));
}
__device__ __forceinline__ void split2(float x0, float x1, uint32_t& hi2, uint32_t& lo2) {
    __nv_bfloat162 h = __floats2bfloat162_rn(x0, x1);
    hi2 = *reinterpret_cast<uint32_t*>(&h);
    float hf0 = __uint_as_float(hi2 << 16);
    float hf1 = __uint_as_float(hi2 & 0xFFFF0000u);
    __nv_bfloat162 l = __floats2bfloat162_rn(x0 - hf0, x1 - hf1);
    lo2 = *reinterpret_cast<uint32_t*>(&l);
}

// ---------------------------------------------------------------------------
// 1) Degree counting + bucket rank: indeg atomic RETURNS this edge's rank
// ---------------------------------------------------------------------------
__global__ void deg_kernel(const int* __restrict__ src, const int* __restrict__ dst) {
    int e = blockIdx.x * blockDim.x + threadIdx.x;
    if (e < N_EDGES) {
        atomicAdd(&g_degout[src[e]], 1.0f);
        g_rank[e] = atomicAdd(&g_degin_i[dst[e]], 1);
    }
}

// ---------------------------------------------------------------------------
// 2) Block-local scan of degin (49 blocks x 1024) + B tile prep (first 4096)
// ---------------------------------------------------------------------------
__global__ __launch_bounds__(1024) void scan1_kernel(const float* __restrict__ fc_w,
                                                     const float* __restrict__ res_w) {
    __shared__ int sh[1024];
    const int t = threadIdx.x, b = blockIdx.x;
    const int node = b * 1024 + t;
    int v = (node < N_NODES) ? g_degin_i[node] : 0;
    sh[t] = v;
    __syncthreads();
#pragma unroll
    for (int off = 1; off < 1024; off <<= 1) {
        int u = (t >= off) ? sh[t - off] : 0;
        __syncthreads();
        sh[t] += u;
        __syncthreads();
    }
    if (node < N_NODES) g_part[node] = sh[t] - v;   // exclusive within block
    if (t == 1023) g_bsum[b] = sh[1023];

    if (node < 4096) {
        int h  = node >> 11;
        int rem = node & 2047;
        int n  = rem >> 4;
        int kb = (rem & 15) * 8;
        const float* W = h ? res_w : fc_w;
        uint32_t hp[4], lp[4];
#pragma unroll
        for (int j = 0; j < 4; j++) {
            uint16_t h0, l0, h1, l1;
            split_bf16(W[(kb + 2 * j)     * DIM + n], h0, l0);
            split_bf16(W[(kb + 2 * j + 1) * DIM + n], h1, l1);
            hp[j] = ((uint32_t)h1 << 16) | h0;
            lp[j] = ((uint32_t)l1 << 16) | l0;
        }
        uint32_t off = (uint32_t)(n * 256 + kb * 2);
        *reinterpret_cast<uint4*>(&g_Bt[(uint32_t)(h * 2)     * 32768u + off]) =
            make_uint4(hp[0], hp[1], hp[2], hp[3]);
        *reinterpret_cast<uint4*>(&g_Bt[(uint32_t)(h * 2 + 1) * 32768u + off]) =
            make_uint4(lp[0], lp[1], lp[2], lp[3]);
    }
}

// ---------------------------------------------------------------------------
// 3) Add-back + norms (warp-parallel base reduction over 49 block sums)
// ---------------------------------------------------------------------------
__global__ __launch_bounds__(1024) void scan2_kernel() {
    __shared__ int base_sh;
    const int t = threadIdx.x, b = blockIdx.x;
    if (t < 32) {
        int v = 0;
        for (int i = t; i < SCAN_BLOCKS; i += 32) v += (i < b) ? g_bsum[i] : 0;
#pragma unroll
        for (int o = 16; o > 0; o >>= 1) v += __shfl_xor_sync(0xFFFFFFFFu, v, o);
        if (t == 0) base_sh = v;
    }
    __syncthreads();
    const int base = base_sh;
    const int node = b * 1024 + t;
    if (node < N_NODES) {
        g_off[node] = base + g_part[node];
        g_outnorm[node] = rsqrtf(fmaxf(g_degout[node], 1.0f));
        g_innorm[node]  = rsqrtf(fmaxf((float)g_degin_i[node], 1.0f));
    }
    if (b == SCAN_BLOCKS - 1 && t == 1023) g_off[N_NODES] = N_EDGES;
}

// ---------------------------------------------------------------------------
// 4) Scatter (PROFILED): no atomics, 1 edge/thread for max occupancy/MLP.
// ---------------------------------------------------------------------------
__global__ void scatter_kernel(const int* __restrict__ src, const int* __restrict__ dst) {
    int e = blockIdx.x * blockDim.x + threadIdx.x;
    if (e < N_EDGES) {
        int d = dst[e];
        g_ssrc[__ldg(&g_off[d]) + g_rank[e]] = src[e];
    }
}

// ---------------------------------------------------------------------------
// 5) CSR aggregation (measured 27us — at L2 roofline): warp/node, MLP=8
// ---------------------------------------------------------------------------
__global__ __launch_bounds__(256) void agg_kernel(const float* __restrict__ feat) {
    const int warp = blockIdx.x * (blockDim.x >> 5) + (threadIdx.x >> 5);
    const int lane = threadIdx.x & 31;
    if (warp >= N_NODES) return;
    const int beg = g_off[warp];
    const int end = g_off[warp + 1];
    const float4* f4 = reinterpret_cast<const float4*>(feat);

    float4 a0 = make_float4(0.f, 0.f, 0.f, 0.f);
    float4 a1 = make_float4(0.f, 0.f, 0.f, 0.f);

    int e = beg;
    for (; e + 8 <= end; e += 8) {
        int s[8];
#pragma unroll
        for (int j = 0; j < 8; j++) s[j] = __ldg(&g_ssrc[e + j]);
        float on[8];
#pragma unroll
        for (int j = 0; j < 8; j++) on[j] = __ldg(&g_outnorm[s[j]]);
        float4 v[8];
#pragma unroll
        for (int j = 0; j < 8; j++) v[j] = f4[(size_t)s[j] * 32 + lane];
#pragma unroll
        for (int j = 0; j < 8; j += 2) {
            a0.x = fmaf(v[j].x, on[j], a0.x);
            a0.y = fmaf(v[j].y, on[j], a0.y);
            a0.z = fmaf(v[j].z, on[j], a0.z);
            a0.w = fmaf(v[j].w, on[j], a0.w);
            a1.x = fmaf(v[j + 1].x, on[j + 1], a1.x);
            a1.y = fmaf(v[j + 1].y, on[j + 1], a1.y);
            a1.z = fmaf(v[j + 1].z, on[j + 1], a1.z);
            a1.w = fmaf(v[j + 1].w, on[j + 1], a1.w);
        }
    }
    if (e + 4 <= end) {
        int s[4];
#pragma unroll
        for (int j = 0; j < 4; j++) s[j] = __ldg(&g_ssrc[e + j]);
        float on[4];
#pragma unroll
        for (int j = 0; j < 4; j++) on[j] = __ldg(&g_outnorm[s[j]]);
        float4 v[4];
#pragma unroll
        for (int j = 0; j < 4; j++) v[j] = f4[(size_t)s[j] * 32 + lane];
#pragma unroll
        for (int j = 0; j < 4; j += 2) {
            a0.x = fmaf(v[j].x, on[j], a0.x);
            a0.y = fmaf(v[j].y, on[j], a0.y);
            a0.z = fmaf(v[j].z, on[j], a0.z);
            a0.w = fmaf(v[j].w, on[j], a0.w);
            a1.x = fmaf(v[j + 1].x, on[j + 1], a1.x);
            a1.y = fmaf(v[j + 1].y, on[j + 1], a1.y);
            a1.z = fmaf(v[j + 1].z, on[j + 1], a1.z);
            a1.w = fmaf(v[j + 1].w, on[j + 1], a1.w);
        }
        e += 4;
    }
    for (; e < end; e++) {
        int s0 = __ldg(&g_ssrc[e]);
        float on = __ldg(&g_outnorm[s0]);
        float4 v = f4[(size_t)s0 * 32 + lane];
        a0.x = fmaf(v.x, on, a0.x);
        a0.y = fmaf(v.y, on, a0.y);
        a0.z = fmaf(v.z, on, a0.z);
        a0.w = fmaf(v.w, on, a0.w);
    }
    a0.x += a1.x; a0.y += a1.y; a0.z += a1.z; a0.w += a1.w;
    reinterpret_cast<float4*>(g_agg)[(size_t)warp * 32 + lane] = a0;
}

// ---------------------------------------------------------------------------
// 6) Persistent mma.sync bf16 GEMM + bias + LayerNorm + ReLU (R10 version)
// ---------------------------------------------------------------------------
#define ROW_BYTES 272
#define TILE_BYTES (128 * ROW_BYTES)
#define SMEM_B     0
#define SMEM_A_HI  (4 * TILE_BYTES)
#define SMEM_A_LO  (SMEM_A_HI + TILE_BYTES)
#define SMEM_STATS (SMEM_A_LO + TILE_BYTES)
#define SMEM_TOTAL (SMEM_STATS + 4096)

__device__ __forceinline__ uint32_t smem_u32(const void* p) {
    uint32_t a;
    asm("{ .reg .u64 t; cvta.to.shared.u64 t, %1; cvt.u32.u64 %0, t; }"
        : "=r"(a) : "l"(p));
    return a;
}
__device__ __forceinline__ void ldsm4(uint32_t (&r)[4], uint32_t addr) {
    asm volatile("ldmatrix.sync.aligned.m8n8.x4.shared.b16 {%0,%1,%2,%3}, [%4];"
                 : "=r"(r[0]), "=r"(r[1]), "=r"(r[2]), "=r"(r[3]) : "r"(addr));
}
__device__ __forceinline__ void mma16816(float (&d)[4], const uint32_t (&a)[4],
                                         uint32_t b0, uint32_t b1) {
    asm volatile("mma.sync.aligned.m16n8k16.row.col.f32.bf16.bf16.f32 "
                 "{%0,%1,%2,%3}, {%4,%5,%6,%7}, {%8,%9}, {%0,%1,%2,%3};"
                 : "+f"(d[0]), "+f"(d[1]), "+f"(d[2]), "+f"(d[3])
                 : "r"(a[0]), "r"(a[1]), "r"(a[2]), "r"(a[3]), "r"(b0), "r"(b1));
}
#define BAR_GRP(id) asm volatile("bar.sync %0, %1;" :: "r"((id) + 1), "r"(128) : "memory")

__global__ __launch_bounds__(512) void gemm_mma_kernel(
    const float* __restrict__ feat,
    const float* __restrict__ fc_b,
    const float* __restrict__ ln_g,
    const float* __restrict__ ln_b,
    float* __restrict__ out)
{
    extern __shared__ __align__(16) char smem[];
    const uint32_t sb = smem_u32(smem);
    const int tid  = threadIdx.x;
    const int wid  = tid >> 5;
    const int lane = tid & 31;
    const int wm   = wid & 3;
    const int wn   = wid >> 2;
    const int gt   = ((wid >> 2) << 5) | lane;

    {
        const uint4* src = reinterpret_cast<const uint4*>(g_Bt);
#pragma unroll
        for (int i = 0; i < 16; i++) {
            int idx = tid + i * 512;
            int t = idx >> 11, rem = idx & 2047;
            int n = rem >> 4, c = rem & 15;
            uint4 v = src[t * 2048 + n * 16 + c];
            *reinterpret_cast<uint4*>(smem + SMEM_B + t * TILE_BYTES + n * ROW_BYTES + c * 16) = v;
        }
    }
    __syncthreads();

    const uint32_t lane_off = (uint32_t)((lane & 15) * ROW_BYTES + (lane >> 4) * 16);
    const int r = lane >> 2, q = lane & 3;
    float2* stats = reinterpret_cast<float2*>(smem + SMEM_STATS);
    const int lr0 = gt >> 4;
    const int lkb = (gt & 15) * 8;

    for (int tile = blockIdx.x; tile < N_TILES; tile += gridDim.x) {
        const int bm0 = tile * 128;

        auto load_a_slice = [&](int half) {
            const float* Ap = half ? feat : g_agg;
#pragma unroll
            for (int pass = 0; pass < 4; pass++) {
                int row_l = wm * 32 + pass * 8 + lr0;
                int row_g = bm0 + row_l;
                float x[8];
                if (row_g < N_NODES) {
                    float4 v0 = *reinterpret_cast<const float4*>(Ap + (size_t)row_g * DIM + lkb);
                    float4 v1 = *reinterpret_cast<const float4*>(Ap + (size_t)row_g * DIM + lkb + 4);
                    x[0]=v0.x; x[1]=v0.y; x[2]=v0.z; x[3]=v0.w;
                    x[4]=v1.x; x[5]=v1.y; x[6]=v1.z; x[7]=v1.w;
                    if (half == 0) {
                        float s = g_innorm[row_g];
#pragma unroll
                        for (int j = 0; j < 8; j++) x[j] *= s;
                    }
                } else {
#pragma unroll
                    for (int j = 0; j < 8; j++) x[j] = 0.0f;
                }
                uint32_t hp[4], lp[4];
#pragma unroll
                for (int j = 0; j < 4; j++)
                    split2(x[2 * j], x[2 * j + 1], hp[j], lp[j]);
                uint32_t off = (uint32_t)(row_l * ROW_BYTES + lkb * 2);
                *reinterpret_cast<uint4*>(smem + SMEM_A_HI + off) = make_uint4(hp[0], hp[1], hp[2], hp[3]);
                *reinterpret_cast<uint4*>(smem + SMEM_A_LO + off) = make_uint4(lp[0], lp[1], lp[2], lp[3]);
            }
        };

        float acc[2][4][4];
#pragma unroll
        for (int m = 0; m < 2; m++)
#pragma unroll
            for (int n = 0; n < 4; n++)
#pragma unroll
                for (int c = 0; c < 4; c++) acc[m][n][c] = 0.0f;

        auto compute_half = [&](int half) {
            const uint32_t bhi0 = sb + SMEM_B + (uint32_t)(half * 2) * TILE_BYTES
                                + (uint32_t)(wn * 32) * ROW_BYTES;
            const uint32_t blo0 = bhi0 + TILE_BYTES;
            const uint32_t ahi0 = sb + SMEM_A_HI + (uint32_t)(wm * 32) * ROW_BYTES;
            const uint32_t alo0 = sb + SMEM_A_LO + (uint32_t)(wm * 32) * ROW_BYTES;
#pragma unroll 2
            for (int ks = 0; ks < 8; ks++) {
                const uint32_t koff = (uint32_t)(ks * 32) + lane_off;
                uint32_t ah[2][4], al[2][4], bh[2][4], bl[2][4];
                ldsm4(ah[0], ahi0 + koff);
                ldsm4(ah[1], ahi0 + 16 * ROW_BYTES + koff);
                ldsm4(al[0], alo0 + koff);
                ldsm4(al[1], alo0 + 16 * ROW_BYTES + koff);
                ldsm4(bh[0], bhi0 + koff);
                ldsm4(bh[1], bhi0 + 16 * ROW_BYTES + koff);
                ldsm4(bl[0], blo0 + koff);
                ldsm4(bl[1], blo0 + 16 * ROW_BYTES + koff);
#pragma unroll
                for (int ng = 0; ng < 2; ng++)
#pragma unroll
                    for (int m = 0; m < 2; m++) {
                        mma16816(acc[m][2 * ng],     ah[m], bh[ng][0], bh[ng][2]);
                        mma16816(acc[m][2 * ng + 1], ah[m], bh[ng][1], bh[ng][3]);
                    }
#pragma unroll
                for (int ng = 0; ng < 2; ng++)
#pragma unroll
                    for (int m = 0; m < 2; m++) {
                        mma16816(acc[m][2 * ng],     ah[m], bl[ng][0], bl[ng][2]);
                        mma16816(acc[m][2 * ng + 1], ah[m], bl[ng][1], bl[ng][3]);
                    }
#pragma unroll
                for (int ng = 0; ng < 2; ng++)
#pragma unroll
                    for (int m = 0; m < 2; m++) {
                        mma16816(acc[m][2 * ng],     al[m], bh[ng][0], bh[ng][2]);
                        mma16816(acc[m][2 * ng + 1], al[m], bh[ng][1], bh[ng][3]);
                    }
            }
        };

        load_a_slice(0);
        BAR_GRP(wm);
        compute_half(0);
        BAR_GRP(wm);
        load_a_slice(1);
        BAR_GRP(wm);
        compute_half(1);

        int rowl[4];
        float innm[4];
#pragma unroll
        for (int mf = 0; mf < 2; mf++)
#pragma unroll
            for (int s = 0; s < 2; s++) {
                int i = mf * 2 + s;
                rowl[i] = wm * 32 + mf * 16 + s * 8 + r;
                int row_g = bm0 + rowl[i];
                innm[i] = (row_g < N_NODES) ? g_innorm[row_g] : 0.0f;
            }

        float s1[4] = {0.f, 0.f, 0.f, 0.f}, s2[4] = {0.f, 0.f, 0.f, 0.f};
#pragma unroll
        for (int nf = 0; nf < 4; nf++) {
            int col = wn * 32 + nf * 8 + q * 2;
            float2 bs = *reinterpret_cast<const float2*>(fc_b + col);
#pragma unroll
            for (int mf = 0; mf < 2; mf++)
#pragma unroll
                for (int s = 0; s < 2; s++) {
                    int i = mf * 2 + s;
                    float x = acc[mf][nf][s * 2]     + innm[i] * bs.x;
                    float y = acc[mf][nf][s * 2 + 1] + innm[i] * bs.y;
                    acc[mf][nf][s * 2] = x;
                    acc[mf][nf][s * 2 + 1] = y;
                    s1[i] += x + y;
                    s2[i] += x * x + y * y;
                }
        }
#pragma unroll
        for (int o = 1; o <= 2; o <<= 1)
#pragma unroll
            for (int i = 0; i < 4; i++) {
                s1[i] += __shfl_xor_sync(0xFFFFFFFFu, s1[i], o);
                s2[i] += __shfl_xor_sync(0xFFFFFFFFu, s2[i], o);
            }

        if (q == 0) {
#pragma unroll
            for (int i = 0; i < 4; i++)
                stats[rowl[i] * 4 + wn] = make_float2(s1[i], s2[i]);
        }
        BAR_GRP(wm);

        float mu[4], inv[4];
#pragma unroll
        for (int i = 0; i < 4; i++) {
            float2 a0 = stats[rowl[i] * 4 + 0];
            float2 a1 = stats[rowl[i] * 4 + 1];
            float2 a2 = stats[rowl[i] * 4 + 2];
            float2 a3 = stats[rowl[i] * 4 + 3];
            float S = a0.x + a1.x + a2.x + a3.x;
            float S2 = a0.y + a1.y + a2.y + a3.y;
            mu[i] = S * (1.0f / DIM);
            float var = S2 * (1.0f / DIM) - mu[i] * mu[i];
            inv[i] = rsqrtf(var + LN_EPS);
        }

#pragma unroll
        for (int nf = 0; nf < 4; nf++) {
            int col = wn * 32 + nf * 8 + q * 2;
            float2 g2 = *reinterpret_cast<const float2*>(ln_g + col);
            float2 b2 = *reinterpret_cast<const float2*>(ln_b + col);
#pragma unroll
            for (int mf = 0; mf < 2; mf++)
#pragma unroll
                for (int s = 0; s < 2; s++) {
                    int i = mf * 2 + s;
                    int row_g = bm0 + rowl[i];
                    if (row_g < N_NODES) {
                        float2 o;
                        o.x = fmaxf((acc[mf][nf][s * 2]     - mu[i]) * inv[i] * g2.x + b2.x, 0.f);
                        o.y = fmaxf((acc[mf][nf][s * 2 + 1] - mu[i]) * inv[i] * g2.y + b2.y, 0.f);
                        *reinterpret_cast<float2*>(out + (size_t)row_g * DIM + col) = o;
                    }
                }
        }
        BAR_GRP(wm);
    }
}

// ---------------------------------------------------------------------------
extern "C" void kernel_launch(void* const* d_in, const int* in_sizes, int n_in,
                              void* d_out, int out_size) {
    const float* feat  = (const float*)d_in[0];
    const int*   src   = (const int*)d_in[1];
    const int*   dst   = (const int*)d_in[2];
    const float* fc_w  = (const float*)d_in[3];
    const float* fc_b  = (const float*)d_in[4];
    const float* res_w = (const float*)d_in[5];
    const float* ln_g  = (const float*)d_in[6];
    const float* ln_b  = (const float*)d_in[7];
    float* out = (float*)d_out;

    void *dout_p, *din_p;
    cudaGetSymbolAddress(&dout_p, g_degout);
    cudaGetSymbolAddress(&din_p, g_degin_i);
    cudaMemsetAsync(dout_p, 0, sizeof(float) * N_NODES);
    cudaMemsetAsync(din_p, 0, sizeof(int) * N_NODES);

    // launch order: scatter is kernel #4 (the one ncu profiles)
    deg_kernel<<<(N_EDGES + 255) / 256, 256>>>(src, dst);
    scan1_kernel<<<SCAN_BLOCKS, 1024>>>(fc_w, res_w);
    scan2_kernel<<<SCAN_BLOCKS, 1024>>>();
    scatter_kernel<<<(N_EDGES + 255) / 256, 256>>>(src, dst);
    agg_kernel<<<(N_NODES * 32 + 255) / 256, 256>>>(feat);

    cudaFuncSetAttribute(gemm_mma_kernel,
                         cudaFuncAttributeMaxDynamicSharedMemorySize, SMEM_TOTAL);
    gemm_mma_kernel<<<148, 512, SMEM_TOTAL>>>(feat, fc_b, ln_g, ln_b, out);
}